// round 1
// baseline (speedup 1.0000x reference)
#include <cuda_runtime.h>

#define B_SZ   4
#define N_SZ   1024
#define DIN    128
#define DOUT   64
#define ITILE  4
#define JCHUNK 128
#define PAD    129          // x2s row pad -> conflict-free transposed writes & reads
#define NBLK_PER_B (N_SZ / ITILE)   // 256

// scratch (static device globals: no allocation)
__device__ float g_x1[B_SZ * N_SZ * DOUT];
__device__ float g_x2[B_SZ * N_SZ * DOUT];

__device__ __forceinline__ float lrelu(float v) {
    return v >= 0.0f ? v : 0.01f * v;
}

// ---------------------------------------------------------------------------
// Kernel 1: x1 = x@w1, x2 = x@w2   (one row per block, 64 threads)
// ---------------------------------------------------------------------------
__global__ void __launch_bounds__(64) proj_kernel(
    const float* __restrict__ x,
    const float* __restrict__ w1,
    const float* __restrict__ w2)
{
    __shared__ float xs[DIN];
    const int row = blockIdx.x;          // 0..4095 flat (b,n)
    const int t   = threadIdx.x;         // 0..63

    xs[t]      = x[row * DIN + t];
    xs[t + 64] = x[row * DIN + t + 64];
    __syncthreads();

    float s1 = 0.0f, s2 = 0.0f;
#pragma unroll 8
    for (int d = 0; d < DIN; ++d) {
        const float xv = xs[d];
        s1 += xv * w1[d * DOUT + t];     // coalesced across t
        s2 += xv * w2[d * DOUT + t];
    }
    g_x1[row * DOUT + t] = s1;
    g_x2[row * DOUT + t] = s2;
}

// ---------------------------------------------------------------------------
// Kernel 2: fused score -> exp/mask -> aggregate -> linear -> lrelu
// One block = ITILE consecutive i-rows of one batch. 128 threads.
// ---------------------------------------------------------------------------
__global__ void __launch_bounds__(128) gat_main_kernel(
    const float* __restrict__ x,       // [B,N,DIN]
    const float* __restrict__ mask,    // [B,N,N]
    const float* __restrict__ a,       // [DOUT]
    const float* __restrict__ lin_w,   // [DOUT,DIN]
    float* __restrict__ out)           // [B,N,DOUT]
{
    __shared__ float  x2s[DOUT * PAD];       // transposed [d][j], padded
    __shared__ float4 ws[JCHUNK];            // per-j weights for 4 rows
    __shared__ float  x1s[ITILE][DOUT];
    __shared__ float  a_s[DOUT];
    __shared__ float  outv[ITILE][DIN];
    __shared__ float  red[ITILE][4];         // per-warp rowsum partials

    const int t  = threadIdx.x;              // 0..127
    const int b  = blockIdx.x >> 8;          // /256
    const int i0 = (blockIdx.x & 255) * ITILE;

    // load x1 rows (contiguous) and attention vector a
    for (int l = t; l < ITILE * DOUT; l += 128)
        ((float*)x1s)[l] = g_x1[(b * N_SZ + i0) * DOUT + l];
    if (t < DOUT) a_s[t] = a[t];

    float acc0 = 0.f, acc1 = 0.f, acc2 = 0.f, acc3 = 0.f;
    float rs0 = 0.f, rs1 = 0.f, rs2 = 0.f, rs3 = 0.f;

    for (int jc = 0; jc < N_SZ / JCHUNK; ++jc) {
        __syncthreads();   // protect x2s/ws still in use from previous chunk

        // stage x2 chunk transposed: coalesced global read, conflict-free write
        const float* x2g = g_x2 + (b * N_SZ + jc * JCHUNK) * DOUT;
        for (int l = t; l < JCHUNK * DOUT; l += 128) {
            const int j = l >> 6;            // /DOUT
            const int d = l & 63;
            x2s[d * PAD + j] = x2g[l];
        }
        __syncthreads();

        // ---- score phase: thread t owns column j = jc*128 + t ----
        float S0 = 0.f, S1 = 0.f, S2 = 0.f, S3 = 0.f;
#pragma unroll
        for (int d = 0; d < DOUT; ++d) {
            const float xv = x2s[d * PAD + t];   // conflict-free
            const float ad = a_s[d];             // broadcast
            S0 += lrelu(x1s[0][d] + xv) * ad;
            S1 += lrelu(x1s[1][d] + xv) * ad;
            S2 += lrelu(x1s[2][d] + xv) * ad;
            S3 += lrelu(x1s[3][d] + xv) * ad;
        }
        const int j = jc * JCHUNK + t;
        const float* mrow = mask + ((size_t)b * N_SZ + i0) * N_SZ + j;
        float4 w;
        w.x = __expf(8.0f * tanhf(S0 * 0.125f)) * mrow[0];
        w.y = __expf(8.0f * tanhf(S1 * 0.125f)) * mrow[N_SZ];
        w.z = __expf(8.0f * tanhf(S2 * 0.125f)) * mrow[2 * N_SZ];
        w.w = __expf(8.0f * tanhf(S3 * 0.125f)) * mrow[3 * N_SZ];
        rs0 += w.x; rs1 += w.y; rs2 += w.z; rs3 += w.w;
        ws[t] = w;
        __syncthreads();

        // ---- aggregation: thread t owns feature dim d = t ----
        const float* xg = x + ((size_t)b * N_SZ + jc * JCHUNK) * DIN + t;
#pragma unroll 8
        for (int jj = 0; jj < JCHUNK; ++jj) {
            const float4 wv = ws[jj];            // one LDS.128 broadcast
            const float  xv = xg[jj * DIN];      // coalesced LDG
            acc0 += wv.x * xv;
            acc1 += wv.y * xv;
            acc2 += wv.z * xv;
            acc3 += wv.w * xv;
        }
    }

    // ---- rowsum block-reduce ----
#pragma unroll
    for (int off = 16; off > 0; off >>= 1) {
        rs0 += __shfl_xor_sync(0xFFFFFFFFu, rs0, off);
        rs1 += __shfl_xor_sync(0xFFFFFFFFu, rs1, off);
        rs2 += __shfl_xor_sync(0xFFFFFFFFu, rs2, off);
        rs3 += __shfl_xor_sync(0xFFFFFFFFu, rs3, off);
    }
    const int warp = t >> 5, lane = t & 31;
    if (lane == 0) {
        red[0][warp] = rs0; red[1][warp] = rs1;
        red[2][warp] = rs2; red[3][warp] = rs3;
    }

    // stash aggregated features
    outv[0][t] = acc0; outv[1][t] = acc1;
    outv[2][t] = acc2; outv[3][t] = acc3;
    __syncthreads();

    // ---- epilogue: y[r][k] = lrelu( outv[r] . lin_w[k] ) / rowsum[r] ----
    // 128 threads -> 2 (r,k) outputs each: k = t&63, rows rb and rb+2
    const int k  = t & 63;
    const int rb = t >> 6;   // 0 or 1
    const float* lw = lin_w + k * DIN;
    float y0 = 0.f, y1 = 0.f;
#pragma unroll 8
    for (int d = 0; d < DIN; ++d) {
        const float l = lw[d];                 // L1-streamed per-thread row
        y0 += outv[rb][d]     * l;             // smem broadcast
        y1 += outv[rb + 2][d] * l;
    }
    const float inv0 = 1.0f / (red[rb][0]     + red[rb][1]     + red[rb][2]     + red[rb][3]);
    const float inv1 = 1.0f / (red[rb + 2][0] + red[rb + 2][1] + red[rb + 2][2] + red[rb + 2][3]);
    // lrelu(y/r) = lrelu(y)/r  (rowsum > 0 guaranteed by self-loops)
    out[((size_t)b * N_SZ + i0 + rb)     * DOUT + k] = lrelu(y0) * inv0;
    out[((size_t)b * N_SZ + i0 + rb + 2) * DOUT + k] = lrelu(y1) * inv1;
}

// ---------------------------------------------------------------------------
extern "C" void kernel_launch(void* const* d_in, const int* in_sizes, int n_in,
                              void* d_out, int out_size)
{
    const float* x     = (const float*)d_in[0];   // [4,1024,128]
    const float* A_shp = (const float*)d_in[1];   // [4,1024,1024]
    const float* w1    = (const float*)d_in[2];   // [128,64]
    const float* w2    = (const float*)d_in[3];   // [128,64]
    const float* a     = (const float*)d_in[4];   // [64]
    const float* lin_w = (const float*)d_in[5];   // [64,128]
    float* out = (float*)d_out;                   // [4,1024,64]

    proj_kernel<<<B_SZ * N_SZ, 64>>>(x, w1, w2);
    gat_main_kernel<<<B_SZ * NBLK_PER_B, 128>>>(x, A_shp, a, lin_w, out);
}

// round 2
// speedup vs baseline: 1.4701x; 1.4701x over previous
#include <cuda_runtime.h>

#define B_SZ   4
#define N_SZ   1024
#define DIN    128
#define DOUT   64
#define ITILE  8
#define JCHUNK 128
#define PAD    129
#define NBLK_PER_B (N_SZ / ITILE)   // 128

__device__ float g_x1[B_SZ * N_SZ * DOUT];
__device__ float g_x2[B_SZ * N_SZ * DOUT];

__device__ __forceinline__ float lrelu(float v) {
    return fmaxf(v, 0.01f * v);   // FMUL + FMNMX
}

// ---------------------------------------------------------------------------
// Kernel 1: x1 = x@w1, x2 = x@w2
// ---------------------------------------------------------------------------
__global__ void __launch_bounds__(64) proj_kernel(
    const float* __restrict__ x,
    const float* __restrict__ w1,
    const float* __restrict__ w2)
{
    __shared__ float xs[DIN];
    const int row = blockIdx.x;
    const int t   = threadIdx.x;

    xs[t]      = x[row * DIN + t];
    xs[t + 64] = x[row * DIN + t + 64];
    __syncthreads();

    float s1 = 0.0f, s2 = 0.0f;
#pragma unroll 8
    for (int d = 0; d < DIN; ++d) {
        const float xv = xs[d];
        s1 += xv * w1[d * DOUT + t];
        s2 += xv * w2[d * DOUT + t];
    }
    g_x1[row * DOUT + t] = s1;
    g_x2[row * DOUT + t] = s2;
}

// ---------------------------------------------------------------------------
// Kernel 2: fused score -> exp/mask -> aggregate -> linear -> lrelu
// One block = 8 i-rows of one batch. 128 threads. 1 full wave (512 blocks).
// ---------------------------------------------------------------------------
__global__ void __launch_bounds__(128, 4) gat_main_kernel(
    const float* __restrict__ x,       // [B,N,DIN]
    const float* __restrict__ mask,    // [B,N,N]
    const float* __restrict__ a,       // [DOUT]
    const float* __restrict__ lin_w,   // [DOUT,DIN]
    float* __restrict__ out)           // [B,N,DOUT]
{
    __shared__ float x2s[DOUT * PAD];          // transposed [d][j]
    __shared__ float x1t[DOUT * ITILE];        // transposed [d][r] -> float4 pairs
    __shared__ float a_s[DOUT];
    __shared__ float ws[JCHUNK * ITILE];       // [j][r] weights
    __shared__ float outv[ITILE][DIN];
    __shared__ float red[ITILE][4];

    const int t  = threadIdx.x;                // 0..127
    const int b  = blockIdx.x >> 7;            // / NBLK_PER_B
    const int i0 = (blockIdx.x & (NBLK_PER_B - 1)) * ITILE;

    // stage x1 transposed [d][r] + attention vector
    for (int l = t; l < ITILE * DOUT; l += 128) {
        const int r = l >> 6, d = l & 63;
        x1t[d * ITILE + r] = g_x1[(b * N_SZ + i0 + r) * DOUT + d];
    }
    if (t < DOUT) a_s[t] = a[t];

    float acc[ITILE], rs[ITILE];
#pragma unroll
    for (int r = 0; r < ITILE; ++r) { acc[r] = 0.f; rs[r] = 0.f; }

    for (int jc = 0; jc < N_SZ / JCHUNK; ++jc) {
        // stage x2 chunk transposed (prev readers of x2s finished before prev agg barrier)
        const float* x2g = g_x2 + (b * N_SZ + jc * JCHUNK) * DOUT;
        for (int l = t; l < JCHUNK * DOUT; l += 128) {
            const int j = l >> 6, d = l & 63;
            x2s[d * PAD + j] = x2g[l];
        }
        __syncthreads();

        // ---- score: thread t owns column j = jc*128 + t, 8 rows in registers ----
        float S[ITILE];
#pragma unroll
        for (int r = 0; r < ITILE; ++r) S[r] = 0.f;

#pragma unroll 8
        for (int d = 0; d < DOUT; ++d) {
            const float  xv = x2s[d * PAD + t];                       // conflict-free
            const float  ad = a_s[d];                                 // broadcast
            const float4 xa = *(const float4*)&x1t[d * ITILE];        // broadcast .128
            const float4 xb = *(const float4*)&x1t[d * ITILE + 4];    // broadcast .128
            S[0] += lrelu(xa.x + xv) * ad;
            S[1] += lrelu(xa.y + xv) * ad;
            S[2] += lrelu(xa.z + xv) * ad;
            S[3] += lrelu(xa.w + xv) * ad;
            S[4] += lrelu(xb.x + xv) * ad;
            S[5] += lrelu(xb.y + xv) * ad;
            S[6] += lrelu(xb.z + xv) * ad;
            S[7] += lrelu(xb.w + xv) * ad;
        }

        const int j = jc * JCHUNK + t;
        const float* mrow = mask + ((size_t)b * N_SZ + i0) * N_SZ + j;
        float wv[ITILE];
#pragma unroll
        for (int r = 0; r < ITILE; ++r) {
            // tanh(s/8) = 1 - 2/(exp(s/4)+1)  (accurate: __expf err ~1e-7 rel)
            const float th = 1.0f - 2.0f / (__expf(S[r] * 0.25f) + 1.0f);
            const float w  = __expf(8.0f * th) * mrow[(size_t)r * N_SZ];
            rs[r] += w;
            wv[r] = w;
        }
        *(float4*)&ws[t * ITILE]     = make_float4(wv[0], wv[1], wv[2], wv[3]);
        *(float4*)&ws[t * ITILE + 4] = make_float4(wv[4], wv[5], wv[6], wv[7]);
        __syncthreads();

        // ---- aggregation: thread t owns feature d = t ----
        const float* xg = x + ((size_t)b * N_SZ + jc * JCHUNK) * DIN + t;
#pragma unroll 4
        for (int jj = 0; jj < JCHUNK; ++jj) {
            const float4 w0 = *(const float4*)&ws[jj * ITILE];        // broadcast .128
            const float4 w1 = *(const float4*)&ws[jj * ITILE + 4];    // broadcast .128
            const float  xv = xg[(size_t)jj * DIN];                   // coalesced LDG
            acc[0] += w0.x * xv;  acc[1] += w0.y * xv;
            acc[2] += w0.z * xv;  acc[3] += w0.w * xv;
            acc[4] += w1.x * xv;  acc[5] += w1.y * xv;
            acc[6] += w1.z * xv;  acc[7] += w1.w * xv;
        }
        __syncthreads();   // protect ws/x2s before next chunk rewrites
    }

    // ---- rowsum block-reduce ----
#pragma unroll
    for (int off = 16; off > 0; off >>= 1)
#pragma unroll
        for (int r = 0; r < ITILE; ++r)
            rs[r] += __shfl_xor_sync(0xFFFFFFFFu, rs[r], off);

    const int warp = t >> 5, lane = t & 31;
    if (lane == 0)
#pragma unroll
        for (int r = 0; r < ITILE; ++r) red[r][warp] = rs[r];

#pragma unroll
    for (int r = 0; r < ITILE; ++r) outv[r][t] = acc[r];
    __syncthreads();

    // ---- epilogue: 512 outputs, 4 per thread: k = t&63, rows rb,rb+2,rb+4,rb+6 ----
    const int k  = t & 63;
    const int rb = t >> 6;
    const float* lw = lin_w + k * DIN;
    float y[4] = {0.f, 0.f, 0.f, 0.f};
#pragma unroll 4
    for (int d = 0; d < DIN; d += 4) {
        const float4 l4 = *(const float4*)&lw[d];
#pragma unroll
        for (int q = 0; q < 4; ++q) {
            const float4 o4 = *(const float4*)&outv[rb + 2 * q][d];   // warp-uniform broadcast
            y[q] += o4.x * l4.x + o4.y * l4.y + o4.z * l4.z + o4.w * l4.w;
        }
    }
#pragma unroll
    for (int q = 0; q < 4; ++q) {
        const int r = rb + 2 * q;
        const float inv = 1.0f / (red[r][0] + red[r][1] + red[r][2] + red[r][3]);
        // lrelu(y/rsum) = lrelu(y)/rsum  (rsum > 0: self-loops)
        out[((size_t)b * N_SZ + i0 + r) * DOUT + k] = lrelu(y[q]) * inv;
    }
}

// ---------------------------------------------------------------------------
extern "C" void kernel_launch(void* const* d_in, const int* in_sizes, int n_in,
                              void* d_out, int out_size)
{
    const float* x     = (const float*)d_in[0];   // [4,1024,128]
    const float* A_shp = (const float*)d_in[1];   // [4,1024,1024]
    const float* w1    = (const float*)d_in[2];   // [128,64]
    const float* w2    = (const float*)d_in[3];   // [128,64]
    const float* a     = (const float*)d_in[4];   // [64]
    const float* lin_w = (const float*)d_in[5];   // [64,128]
    float* out = (float*)d_out;                   // [4,1024,64]

    proj_kernel<<<B_SZ * N_SZ, 64>>>(x, w1, w2);
    gat_main_kernel<<<B_SZ * NBLK_PER_B, 128>>>(x, A_shp, a, lin_w, out);
}

// round 3
// speedup vs baseline: 1.7497x; 1.1903x over previous
#include <cuda_runtime.h>

#define B_SZ   4
#define N_SZ   1024
#define DIN    128
#define DOUT   64
#define ITILE  8
#define JCHUNK 128
#define PAD    129
#define NTILES (B_SZ * N_SZ / ITILE)     // 512 i-tiles
#define HALF_CHUNKS 4                    // 4 chunks of 128 j per block

__device__ float g_x1[B_SZ * N_SZ * DOUT];
__device__ float g_x2[B_SZ * N_SZ * DOUT];
__device__ float g_c1[B_SZ * N_SZ];
__device__ float g_c2[B_SZ * N_SZ];
__device__ float g_acc[2 * NTILES * ITILE * DIN];   // [block][r][d]  (4 MB)
__device__ float g_rs [2 * NTILES * ITILE];         // [block][r]

__device__ __forceinline__ float lrelu(float v) { return fmaxf(v, 0.01f * v); }

typedef unsigned long long u64;

__device__ __forceinline__ u64 pk2(float v) {           // dup-pack {v,v}
    u64 r; unsigned u = __float_as_uint(v);
    asm("mov.b64 %0, {%1, %1};" : "=l"(r) : "r"(u)); return r;
}
__device__ __forceinline__ u64 add2(u64 a, u64 b) {
    u64 r; asm("add.rn.f32x2 %0, %1, %2;" : "=l"(r) : "l"(a), "l"(b)); return r;
}
__device__ __forceinline__ u64 fma2(u64 a, u64 b, u64 c) {
    u64 r; asm("fma.rn.f32x2 %0, %1, %2, %3;" : "=l"(r) : "l"(a), "l"(b), "l"(c)); return r;
}
__device__ __forceinline__ void upk(u64 v, float& lo, float& hi) {
    unsigned a, b; asm("mov.b64 {%0, %1}, %2;" : "=r"(a), "=r"(b) : "l"(v));
    lo = __uint_as_float(a); hi = __uint_as_float(b);
}
#define ABS2 0x7FFFFFFF7FFFFFFFULL

// ---------------------------------------------------------------------------
// Kernel 1: x1 = x@w1, x2 = x@w2, c1 = x1.a, c2 = x2.a
// ---------------------------------------------------------------------------
__global__ void __launch_bounds__(64) proj_kernel(
    const float* __restrict__ x,
    const float* __restrict__ w1,
    const float* __restrict__ w2,
    const float* __restrict__ a)
{
    __shared__ float xs[DIN];
    __shared__ float r1[2], r2[2];
    const int row = blockIdx.x;
    const int t   = threadIdx.x;

    xs[t]      = x[row * DIN + t];
    xs[t + 64] = x[row * DIN + t + 64];
    __syncthreads();

    float s1 = 0.0f, s2 = 0.0f;
#pragma unroll 8
    for (int d = 0; d < DIN; ++d) {
        const float xv = xs[d];
        s1 += xv * w1[d * DOUT + t];
        s2 += xv * w2[d * DOUT + t];
    }
    g_x1[row * DOUT + t] = s1;
    g_x2[row * DOUT + t] = s2;

    // dot with a (64 lanes = 2 warps)
    const float av = a[t];
    float p1 = s1 * av, p2 = s2 * av;
#pragma unroll
    for (int off = 16; off > 0; off >>= 1) {
        p1 += __shfl_xor_sync(0xFFFFFFFFu, p1, off);
        p2 += __shfl_xor_sync(0xFFFFFFFFu, p2, off);
    }
    if ((t & 31) == 0) { r1[t >> 5] = p1; r2[t >> 5] = p2; }
    __syncthreads();
    if (t == 0) { g_c1[row] = r1[0] + r1[1]; g_c2[row] = r2[0] + r2[1]; }
}

// ---------------------------------------------------------------------------
// Kernel 2: score + exp/mask + partial aggregation over half the j-range.
// blockIdx = tile*2 + half. 128 threads.
// ---------------------------------------------------------------------------
__global__ void __launch_bounds__(128) gat_score_agg_kernel(
    const float* __restrict__ x,       // [B,N,DIN]
    const float* __restrict__ mask)    // [B,N,N]
{
    __shared__ __align__(16) float x2s[DOUT * PAD];   // [d][j]
    __shared__ __align__(16) float x1f[DOUT * ITILE]; // [d][r], r contiguous
    __shared__ __align__(16) u64   a2s[DOUT];         // dup-packed a
    __shared__ __align__(16) u64   ws2[JCHUNK * 4];   // [j][pair]
    __shared__ float c1s[ITILE];                      // 0.505*c1
    __shared__ float redm[ITILE][4];

    const int t    = threadIdx.x;
    const int bi   = blockIdx.x;
    const int tile = bi >> 1;
    const int half = bi & 1;
    const int b    = tile >> 7;
    const int i0   = (tile & 127) * ITILE;

    // stage x1 transposed [d][r] and packed a
    for (int l = t; l < ITILE * DOUT; l += 128) {
        const int r = l >> 6, d = l & 63;
        x1f[d * ITILE + r] = g_x1[(b * N_SZ + i0 + r) * DOUT + d];
    }
    if (t < DOUT) a2s[t] = pk2(__ldg(&((const float*)g_x1)[0]) * 0.f +  // keep simple: load a via g? no
                               0.f);   // placeholder (overwritten below)
    // NOTE: a is folded into c1/c2 and the |.| sum needs raw a -> store via x? use g: pass a through x? 
    // (real staging below)
    if (t < ITILE) c1s[t] = 0.505f * g_c1[b * N_SZ + i0 + t];

    // proper a2s staging (a lives in g_a)
    extern __device__ float g_a[];
    if (t < DOUT) a2s[t] = pk2(g_a[t]);

    u64 acc[4]; float rs[ITILE];
#pragma unroll
    for (int p = 0; p < 4; ++p) acc[p] = 0ULL;
#pragma unroll
    for (int r = 0; r < ITILE; ++r) rs[r] = 0.f;

    for (int c = 0; c < HALF_CHUNKS; ++c) {
        const int jc = half * HALF_CHUNKS + c;

        // stage x2 chunk transposed: float4 reads, scalar scattered writes
        const float4* x2g4 = (const float4*)(g_x2 + (b * N_SZ + jc * JCHUNK) * DOUT);
        for (int l = t; l < JCHUNK * DOUT / 4; l += 128) {
            const float4 v = x2g4[l];
            const int j = l >> 4;            // 16 float4 per j-row
            const int d = (l & 15) * 4;
            x2s[(d + 0) * PAD + j] = v.x;
            x2s[(d + 1) * PAD + j] = v.y;
            x2s[(d + 2) * PAD + j] = v.z;
            x2s[(d + 3) * PAD + j] = v.w;
        }
        __syncthreads();

        // ---- score: T[r] = sum_d a_d * |x1[r,d] + x2[j,d]|, packed pairs ----
        u64 T[4];
#pragma unroll
        for (int p = 0; p < 4; ++p) T[p] = 0ULL;

#pragma unroll 16
        for (int d = 0; d < DOUT; ++d) {
            const u64 xv2 = pk2(x2s[d * PAD + t]);
            const u64 ad2 = a2s[d];
            const ulonglong2 xa = ((const ulonglong2*)x1f)[d * 2];     // pairs 0,1
            const ulonglong2 xb = ((const ulonglong2*)x1f)[d * 2 + 1]; // pairs 2,3
            T[0] = fma2(add2(xa.x, xv2) & ABS2, ad2, T[0]);
            T[1] = fma2(add2(xa.y, xv2) & ABS2, ad2, T[1]);
            T[2] = fma2(add2(xb.x, xv2) & ABS2, ad2, T[2]);
            T[3] = fma2(add2(xb.y, xv2) & ABS2, ad2, T[3]);
        }

        const int j = jc * JCHUNK + t;
        const float c2j = 0.505f * g_c2[b * N_SZ + j];
        const float* mrow = mask + ((size_t)b * N_SZ + i0) * N_SZ + j;
        float w[ITILE];
#pragma unroll
        for (int p = 0; p < 4; ++p) {
            float t0, t1; upk(T[p], t0, t1);
            const float S0 = fmaf(0.495f, t0, c1s[2 * p]     + c2j);
            const float S1 = fmaf(0.495f, t1, c1s[2 * p + 1] + c2j);
            const float th0 = 1.0f - 2.0f / (__expf(S0 * 0.25f) + 1.0f);
            const float th1 = 1.0f - 2.0f / (__expf(S1 * 0.25f) + 1.0f);
            w[2 * p]     = __expf(8.0f * th0) * mrow[(size_t)(2 * p)     * N_SZ];
            w[2 * p + 1] = __expf(8.0f * th1) * mrow[(size_t)(2 * p + 1) * N_SZ];
            rs[2 * p]     += w[2 * p];
            rs[2 * p + 1] += w[2 * p + 1];
        }
        ((float4*)ws2)[t * 2]     = make_float4(w[0], w[1], w[2], w[3]);
        ((float4*)ws2)[t * 2 + 1] = make_float4(w[4], w[5], w[6], w[7]);
        __syncthreads();

        // ---- aggregation: thread t owns feature d = t, packed row-pairs ----
        const float* xg = x + ((size_t)b * N_SZ + jc * JCHUNK) * DIN + t;
#pragma unroll 4
        for (int jj = 0; jj < JCHUNK; ++jj) {
            const ulonglong2 wA = ((const ulonglong2*)ws2)[jj * 2];
            const ulonglong2 wB = ((const ulonglong2*)ws2)[jj * 2 + 1];
            const u64 xv2 = pk2(xg[(size_t)jj * DIN]);
            acc[0] = fma2(wA.x, xv2, acc[0]);
            acc[1] = fma2(wA.y, xv2, acc[1]);
            acc[2] = fma2(wB.x, xv2, acc[2]);
            acc[3] = fma2(wB.y, xv2, acc[3]);
        }
        __syncthreads();
    }

    // ---- rowsum block-reduce -> scratch ----
#pragma unroll
    for (int off = 16; off > 0; off >>= 1)
#pragma unroll
        for (int r = 0; r < ITILE; ++r)
            rs[r] += __shfl_xor_sync(0xFFFFFFFFu, rs[r], off);
    const int warp = t >> 5, lane = t & 31;
    if (lane == 0)
#pragma unroll
        for (int r = 0; r < ITILE; ++r) redm[r][warp] = rs[r];

    // ---- partial acc -> scratch ----
    float* ap = g_acc + (size_t)bi * ITILE * DIN + t;
#pragma unroll
    for (int p = 0; p < 4; ++p) {
        float lo, hi; upk(acc[p], lo, hi);
        ap[(2 * p) * DIN]     = lo;
        ap[(2 * p + 1) * DIN] = hi;
    }
    __syncthreads();
    if (t < ITILE)
        g_rs[bi * ITILE + t] = redm[t][0] + redm[t][1] + redm[t][2] + redm[t][3];
}

// ---------------------------------------------------------------------------
// Kernel 3: combine halves + normalize-deferred linear + lrelu
// ---------------------------------------------------------------------------
__global__ void __launch_bounds__(128) gat_epilogue_kernel(
    const float* __restrict__ lin_w,   // [DOUT,DIN]
    float* __restrict__ out)           // [B,N,DOUT]
{
    __shared__ float outv[ITILE][DIN];
    __shared__ float red[ITILE];

    const int t    = threadIdx.x;
    const int tile = blockIdx.x;
    const int b    = tile >> 7;
    const int i0   = (tile & 127) * ITILE;

    const float* A0 = g_acc + (size_t)tile * 2 * ITILE * DIN;
#pragma unroll
    for (int r = 0; r < ITILE; ++r)
        outv[r][t] = A0[r * DIN + t] + A0[ITILE * DIN + r * DIN + t];
    if (t < ITILE)
        red[t] = g_rs[tile * 2 * ITILE + t] + g_rs[(tile * 2 + 1) * ITILE + t];
    __syncthreads();

    const int k  = t & 63;
    const int rb = t >> 6;
    const float* lw = lin_w + k * DIN;
    float y[4] = {0.f, 0.f, 0.f, 0.f};
#pragma unroll 4
    for (int d = 0; d < DIN; d += 4) {
        const float4 l4 = *(const float4*)&lw[d];
#pragma unroll
        for (int q = 0; q < 4; ++q) {
            const float4 o4 = *(const float4*)&outv[rb + 2 * q][d];
            y[q] += o4.x * l4.x + o4.y * l4.y + o4.z * l4.z + o4.w * l4.w;
        }
    }
#pragma unroll
    for (int q = 0; q < 4; ++q) {
        const int r = rb + 2 * q;
        const float inv = 1.0f / red[r];
        out[((size_t)b * N_SZ + i0 + r) * DOUT + k] = lrelu(y[q]) * inv;
    }
}

// a must live in device memory reachable by kernel2
__device__ float g_a[DOUT];

__global__ void stage_a_kernel(const float* __restrict__ a) {
    if (threadIdx.x < DOUT) g_a[threadIdx.x] = a[threadIdx.x];
}

// ---------------------------------------------------------------------------
extern "C" void kernel_launch(void* const* d_in, const int* in_sizes, int n_in,
                              void* d_out, int out_size)
{
    const float* x     = (const float*)d_in[0];   // [4,1024,128]
    const float* A_shp = (const float*)d_in[1];   // [4,1024,1024]
    const float* w1    = (const float*)d_in[2];   // [128,64]
    const float* w2    = (const float*)d_in[3];   // [128,64]
    const float* a     = (const float*)d_in[4];   // [64]
    const float* lin_w = (const float*)d_in[5];   // [64,128]
    float* out = (float*)d_out;                   // [4,1024,64]

    stage_a_kernel<<<1, 64>>>(a);
    proj_kernel<<<B_SZ * N_SZ, 64>>>(x, w1, w2, a);
    gat_score_agg_kernel<<<2 * NTILES, 128>>>(x, A_shp);
    gat_epilogue_kernel<<<NTILES, 128>>>(lin_w, out);
}

// round 4
// speedup vs baseline: 1.7930x; 1.0247x over previous
#include <cuda_runtime.h>

#define B_SZ   4
#define N_SZ   1024
#define DIN    128
#define DOUT   64
#define ITILE  8
#define JCHUNK 128
#define PAD    129
#define NTILES (B_SZ * N_SZ / ITILE)     // 512 i-tiles
#define SPLIT  4
#define CHUNKS_PER 2                     // 8 chunks / 4 splits

__device__ float g_x1[B_SZ * N_SZ * DOUT];
__device__ float g_x2[B_SZ * N_SZ * DOUT];
__device__ float g_c1[B_SZ * N_SZ];
__device__ float g_c2[B_SZ * N_SZ];
__device__ float g_acc[SPLIT * NTILES * ITILE * DIN];   // 8 MB
__device__ float g_rs [SPLIT * NTILES * ITILE];

__device__ __forceinline__ float lrelu(float v) { return fmaxf(v, 0.01f * v); }

typedef unsigned long long u64;

__device__ __forceinline__ u64 pk2(float v) {
    u64 r; unsigned u = __float_as_uint(v);
    asm("mov.b64 %0, {%1, %1};" : "=l"(r) : "r"(u)); return r;
}
__device__ __forceinline__ u64 add2(u64 a, u64 b) {
    u64 r; asm("add.rn.f32x2 %0, %1, %2;" : "=l"(r) : "l"(a), "l"(b)); return r;
}
__device__ __forceinline__ u64 fma2(u64 a, u64 b, u64 c) {
    u64 r; asm("fma.rn.f32x2 %0, %1, %2, %3;" : "=l"(r) : "l"(a), "l"(b), "l"(c)); return r;
}
__device__ __forceinline__ void upk(u64 v, float& lo, float& hi) {
    unsigned a, b; asm("mov.b64 {%0, %1}, %2;" : "=r"(a), "=r"(b) : "l"(v));
    lo = __uint_as_float(a); hi = __uint_as_float(b);
}
#define ABS2 0x7FFFFFFF7FFFFFFFULL

// ---------------------------------------------------------------------------
// Kernel 1: x1 = x@w1, x2 = x@w2, c1 = x1.a, c2 = x2.a
// ---------------------------------------------------------------------------
__global__ void __launch_bounds__(64) proj_kernel(
    const float* __restrict__ x,
    const float* __restrict__ w1,
    const float* __restrict__ w2,
    const float* __restrict__ a)
{
    __shared__ float xs[DIN];
    __shared__ float r1[2], r2[2];
    const int row = blockIdx.x;
    const int t   = threadIdx.x;

    xs[t]      = x[row * DIN + t];
    xs[t + 64] = x[row * DIN + t + 64];
    __syncthreads();

    float s1 = 0.0f, s2 = 0.0f;
#pragma unroll 8
    for (int d = 0; d < DIN; ++d) {
        const float xv = xs[d];
        s1 += xv * w1[d * DOUT + t];
        s2 += xv * w2[d * DOUT + t];
    }
    g_x1[row * DOUT + t] = s1;
    g_x2[row * DOUT + t] = s2;

    const float av = a[t];
    float p1 = s1 * av, p2 = s2 * av;
#pragma unroll
    for (int off = 16; off > 0; off >>= 1) {
        p1 += __shfl_xor_sync(0xFFFFFFFFu, p1, off);
        p2 += __shfl_xor_sync(0xFFFFFFFFu, p2, off);
    }
    if ((t & 31) == 0) { r1[t >> 5] = p1; r2[t >> 5] = p2; }
    __syncthreads();
    if (t == 0) { g_c1[row] = r1[0] + r1[1]; g_c2[row] = r2[0] + r2[1]; }
}

// ---------------------------------------------------------------------------
// Kernel 2: score + exp/mask + partial aggregation over a quarter j-range.
// blockIdx = tile*4 + part. 128 threads.
// ---------------------------------------------------------------------------
__global__ void __launch_bounds__(128, 6) gat_score_agg_kernel(
    const float* __restrict__ x,       // [B,N,DIN]
    const float* __restrict__ mask,    // [B,N,N]
    const float* __restrict__ a)       // [DOUT]
{
    __shared__ __align__(16) float pool[DOUT * PAD];   // x2s [d][j]; ws aliased at front
    __shared__ __align__(16) float x1f[DOUT * ITILE];  // [d][r]
    __shared__ __align__(16) u64   a2s[DOUT];
    __shared__ float c1s[ITILE];
    __shared__ float redm[ITILE][4];

    u64* const ws2 = (u64*)pool;   // 4 KB alias: pool rows d=0..7, dead by restage

    const int t    = threadIdx.x;
    const int bi   = blockIdx.x;
    const int tile = bi >> 2;
    const int part = bi & 3;
    const int b    = tile >> 7;
    const int i0   = (tile & 127) * ITILE;

    for (int l = t; l < ITILE * DOUT; l += 128) {
        const int r = l >> 6, d = l & 63;
        x1f[d * ITILE + r] = g_x1[(b * N_SZ + i0 + r) * DOUT + d];
    }
    if (t < DOUT) a2s[t] = pk2(a[t]);
    if (t < ITILE) c1s[t] = 0.505f * g_c1[b * N_SZ + i0 + t];

    u64 acc[4]; float rs[ITILE];
#pragma unroll
    for (int p = 0; p < 4; ++p) acc[p] = 0ULL;
#pragma unroll
    for (int r = 0; r < ITILE; ++r) rs[r] = 0.f;

    for (int c = 0; c < CHUNKS_PER; ++c) {
        const int jc = part * CHUNKS_PER + c;

        // stage x2 chunk transposed (also overwrites the ws alias region)
        const float4* x2g4 = (const float4*)(g_x2 + (b * N_SZ + jc * JCHUNK) * DOUT);
        for (int l = t; l < JCHUNK * DOUT / 4; l += 128) {
            const float4 v = x2g4[l];
            const int j = l >> 4;
            const int d = (l & 15) * 4;
            pool[(d + 0) * PAD + j] = v.x;
            pool[(d + 1) * PAD + j] = v.y;
            pool[(d + 2) * PAD + j] = v.z;
            pool[(d + 3) * PAD + j] = v.w;
        }
        __syncthreads();                                   // A: x2s staged

        // ---- score: T[r] = sum_d a_d * |x1[r,d] + x2[j,d]| ----
        u64 T[4];
#pragma unroll
        for (int p = 0; p < 4; ++p) T[p] = 0ULL;

#pragma unroll 16
        for (int d = 0; d < DOUT; ++d) {
            const u64 xv2 = pk2(pool[d * PAD + t]);
            const u64 ad2 = a2s[d];
            const ulonglong2 xa = ((const ulonglong2*)x1f)[d * 2];
            const ulonglong2 xb = ((const ulonglong2*)x1f)[d * 2 + 1];
            T[0] = fma2(add2(xa.x, xv2) & ABS2, ad2, T[0]);
            T[1] = fma2(add2(xa.y, xv2) & ABS2, ad2, T[1]);
            T[2] = fma2(add2(xb.x, xv2) & ABS2, ad2, T[2]);
            T[3] = fma2(add2(xb.y, xv2) & ABS2, ad2, T[3]);
        }
        __syncthreads();                                   // B: x2s reads done (ws aliases x2s)

        const int j = jc * JCHUNK + t;
        const float c2j = 0.505f * g_c2[b * N_SZ + j];
        const float* mrow = mask + ((size_t)b * N_SZ + i0) * N_SZ + j;
        float w[ITILE];
#pragma unroll
        for (int p = 0; p < 4; ++p) {
            float t0, t1; upk(T[p], t0, t1);
            const float S0 = fmaf(0.495f, t0, c1s[2 * p]     + c2j);
            const float S1 = fmaf(0.495f, t1, c1s[2 * p + 1] + c2j);
            const float th0 = 1.0f - 2.0f / (__expf(S0 * 0.25f) + 1.0f);
            const float th1 = 1.0f - 2.0f / (__expf(S1 * 0.25f) + 1.0f);
            w[2 * p]     = __expf(8.0f * th0) * mrow[(size_t)(2 * p)     * N_SZ];
            w[2 * p + 1] = __expf(8.0f * th1) * mrow[(size_t)(2 * p + 1) * N_SZ];
            rs[2 * p]     += w[2 * p];
            rs[2 * p + 1] += w[2 * p + 1];
        }
        ((float4*)ws2)[t * 2]     = make_float4(w[0], w[1], w[2], w[3]);
        ((float4*)ws2)[t * 2 + 1] = make_float4(w[4], w[5], w[6], w[7]);
        __syncthreads();                                   // C: ws visible

        // ---- aggregation: thread t owns feature d = t ----
        const float* xg = x + ((size_t)b * N_SZ + jc * JCHUNK) * DIN + t;
#pragma unroll 4
        for (int jj = 0; jj < JCHUNK; ++jj) {
            const ulonglong2 wA = ((const ulonglong2*)ws2)[jj * 2];
            const ulonglong2 wB = ((const ulonglong2*)ws2)[jj * 2 + 1];
            const u64 xv2 = pk2(xg[(size_t)jj * DIN]);
            acc[0] = fma2(wA.x, xv2, acc[0]);
            acc[1] = fma2(wA.y, xv2, acc[1]);
            acc[2] = fma2(wB.x, xv2, acc[2]);
            acc[3] = fma2(wB.y, xv2, acc[3]);
        }
        __syncthreads();                                   // D: agg done before restage
    }

#pragma unroll
    for (int off = 16; off > 0; off >>= 1)
#pragma unroll
        for (int r = 0; r < ITILE; ++r)
            rs[r] += __shfl_xor_sync(0xFFFFFFFFu, rs[r], off);
    const int warp = t >> 5, lane = t & 31;
    if (lane == 0)
#pragma unroll
        for (int r = 0; r < ITILE; ++r) redm[r][warp] = rs[r];

    float* ap = g_acc + (size_t)bi * ITILE * DIN + t;
#pragma unroll
    for (int p = 0; p < 4; ++p) {
        float lo, hi; upk(acc[p], lo, hi);
        ap[(2 * p) * DIN]     = lo;
        ap[(2 * p + 1) * DIN] = hi;
    }
    __syncthreads();
    if (t < ITILE)
        g_rs[bi * ITILE + t] = redm[t][0] + redm[t][1] + redm[t][2] + redm[t][3];
}

// ---------------------------------------------------------------------------
// Kernel 3: combine 4 partials + linear + lrelu. 256 threads, 2 outputs each.
// ---------------------------------------------------------------------------
__global__ void __launch_bounds__(256) gat_epilogue_kernel(
    const float* __restrict__ lin_w,   // [DOUT,DIN]
    float* __restrict__ out)           // [B,N,DOUT]
{
    __shared__ float outv[ITILE][DIN];
    __shared__ float red[ITILE];

    const int t    = threadIdx.x;
    const int tile = blockIdx.x;
    const int b    = tile >> 7;
    const int i0   = (tile & 127) * ITILE;

    const float* base = g_acc + (size_t)tile * SPLIT * ITILE * DIN;
    for (int l = t; l < ITILE * DIN; l += 256) {
        float s = base[l];
#pragma unroll
        for (int p = 1; p < SPLIT; ++p) s += base[p * ITILE * DIN + l];
        ((float*)outv)[l] = s;
    }
    if (t < ITILE) {
        float s = 0.f;
#pragma unroll
        for (int p = 0; p < SPLIT; ++p) s += g_rs[(tile * SPLIT + p) * ITILE + t];
        red[t] = s;
    }
    __syncthreads();

    const int k  = t & 63;
    const int rg = t >> 6;            // 0..3 -> rows rg, rg+4
    const float* lw = lin_w + k * DIN;
    float y0 = 0.f, y1 = 0.f;
#pragma unroll 8
    for (int d = 0; d < DIN; d += 4) {
        const float4 l4 = *(const float4*)&lw[d];
        const float4 oa = *(const float4*)&outv[rg][d];
        const float4 ob = *(const float4*)&outv[rg + 4][d];
        y0 += oa.x * l4.x + oa.y * l4.y + oa.z * l4.z + oa.w * l4.w;
        y1 += ob.x * l4.x + ob.y * l4.y + ob.z * l4.z + ob.w * l4.w;
    }
    const float inv0 = 1.0f / red[rg];
    const float inv1 = 1.0f / red[rg + 4];
    out[((size_t)b * N_SZ + i0 + rg)     * DOUT + k] = lrelu(y0) * inv0;
    out[((size_t)b * N_SZ + i0 + rg + 4) * DOUT + k] = lrelu(y1) * inv1;
}

// ---------------------------------------------------------------------------
extern "C" void kernel_launch(void* const* d_in, const int* in_sizes, int n_in,
                              void* d_out, int out_size)
{
    const float* x     = (const float*)d_in[0];
    const float* A_shp = (const float*)d_in[1];
    const float* w1    = (const float*)d_in[2];
    const float* w2    = (const float*)d_in[3];
    const float* a     = (const float*)d_in[4];
    const float* lin_w = (const float*)d_in[5];
    float* out = (float*)d_out;

    proj_kernel<<<B_SZ * N_SZ, 64>>>(x, w1, w2, a);
    gat_score_agg_kernel<<<SPLIT * NTILES, 128>>>(x, A_shp, a);
    gat_epilogue_kernel<<<NTILES, 256>>>(lin_w, out);
}